// round 1
// baseline (speedup 1.0000x reference)
#include <cuda_runtime.h>
#include <cuda_bf16.h>
#include <math.h>

#define D_MODEL 2048
#define NHEADS  16
#define DHEAD   128
#define TSEQ    2048
#define BATCH   2
#define MROWS   (BATCH * TSEQ)   // 4096

// Scratch (allocation-free rule: static __device__ arrays)
__device__ float g_q[(size_t)MROWS * D_MODEL];
__device__ float g_k[(size_t)MROWS * D_MODEL];
__device__ float g_v[(size_t)MROWS * D_MODEL];
__device__ float g_o[(size_t)MROWS * D_MODEL];

// ---------------------------------------------------------------------------
// GEMM: C = A @ W^T + bias
// A [M,K] row-major, W [N,K] row-major (torch Linear weight), C [M,N]
// BM=BN=128, BK=16, 256 threads, 8x8 microtile.
// blockIdx.z selects among up to 3 (W, bias, C) triples (QKV fused launch).
// ---------------------------------------------------------------------------
__global__ void __launch_bounds__(256) gemm_bias_kernel(
    const float* __restrict__ A,
    const float* __restrict__ W0, const float* __restrict__ W1, const float* __restrict__ W2,
    const float* __restrict__ b0, const float* __restrict__ b1, const float* __restrict__ b2,
    float* __restrict__ C0, float* __restrict__ C1, float* __restrict__ C2)
{
    const float* W;
    const float* bias;
    float* C;
    if (blockIdx.z == 0)      { W = W0; bias = b0; C = C0; }
    else if (blockIdx.z == 1) { W = W1; bias = b1; C = C1; }
    else                      { W = W2; bias = b2; C = C2; }

    __shared__ float As[16][128];   // k-major: As[k][m]
    __shared__ float Bs[16][128];   // k-major: Bs[k][n]

    const int t  = threadIdx.x;
    const int tx = t & 15;
    const int ty = t >> 4;
    const int m0 = blockIdx.y * 128;
    const int n0 = blockIdx.x * 128;

    // loader indices: thread covers row lr, k-offsets {kc, kc+4}
    const int lr = t >> 1;
    const int kc = (t & 1) * 8;

    float acc[8][8];
#pragma unroll
    for (int i = 0; i < 8; i++)
#pragma unroll
        for (int j = 0; j < 8; j++) acc[i][j] = 0.0f;

    const float* Arow = A + (size_t)(m0 + lr) * D_MODEL;
    const float* Wrow = W + (size_t)(n0 + lr) * D_MODEL;

    for (int k0 = 0; k0 < D_MODEL; k0 += 16) {
#pragma unroll
        for (int h = 0; h < 2; h++) {
            int kk = kc + h * 4;
            float4 va = *(const float4*)&Arow[k0 + kk];
            As[kk + 0][lr] = va.x; As[kk + 1][lr] = va.y;
            As[kk + 2][lr] = va.z; As[kk + 3][lr] = va.w;
            float4 vb = *(const float4*)&Wrow[k0 + kk];
            Bs[kk + 0][lr] = vb.x; Bs[kk + 1][lr] = vb.y;
            Bs[kk + 2][lr] = vb.z; Bs[kk + 3][lr] = vb.w;
        }
        __syncthreads();

#pragma unroll
        for (int kk = 0; kk < 16; kk++) {
            float a[8], b[8];
            *(float4*)&a[0] = *(const float4*)&As[kk][ty * 8];
            *(float4*)&a[4] = *(const float4*)&As[kk][ty * 8 + 4];
            *(float4*)&b[0] = *(const float4*)&Bs[kk][tx * 8];
            *(float4*)&b[4] = *(const float4*)&Bs[kk][tx * 8 + 4];
#pragma unroll
            for (int i = 0; i < 8; i++)
#pragma unroll
                for (int j = 0; j < 8; j++)
                    acc[i][j] = fmaf(a[i], b[j], acc[i][j]);
        }
        __syncthreads();
    }

    // epilogue: + bias, store
    float bj[8];
#pragma unroll
    for (int j = 0; j < 8; j++) bj[j] = bias[n0 + tx * 8 + j];

#pragma unroll
    for (int i = 0; i < 8; i++) {
        const int m = m0 + ty * 8 + i;
        float* crow = C + (size_t)m * D_MODEL + n0 + tx * 8;
        float4 r0, r1;
        r0.x = acc[i][0] + bj[0]; r0.y = acc[i][1] + bj[1];
        r0.z = acc[i][2] + bj[2]; r0.w = acc[i][3] + bj[3];
        r1.x = acc[i][4] + bj[4]; r1.y = acc[i][5] + bj[5];
        r1.z = acc[i][6] + bj[6]; r1.w = acc[i][7] + bj[7];
        *(float4*)&crow[0] = r0;
        *(float4*)&crow[4] = r1;
    }
}

// ---------------------------------------------------------------------------
// RoPE in-place on g_q and g_k, layout (B,T,H,D) == [B*T, 2048].
// One thread per (row, head, pair i<64).
// ---------------------------------------------------------------------------
__global__ void rope_kernel(const float* __restrict__ sin_t,
                            const float* __restrict__ cos_t)
{
    int idx = blockIdx.x * blockDim.x + threadIdx.x;   // B*T*H*64 = 4,194,304
    if (idx >= MROWS * NHEADS * 64) return;
    int i   = idx & 63;
    int h   = (idx >> 6) & (NHEADS - 1);
    int row = idx >> 10;                // b*T + t
    int tpos = row & (TSEQ - 1);

    float s = sin_t[tpos * 64 + i];
    float c = cos_t[tpos * 64 + i];

    size_t base = (size_t)row * D_MODEL + h * DHEAD + i;
    float q1 = g_q[base], q2 = g_q[base + 64];
    g_q[base]      = q1 * c - q2 * s;
    g_q[base + 64] = q1 * s + q2 * c;
    float k1 = g_k[base], k2 = g_k[base + 64];
    g_k[base]      = k1 * c - k2 * s;
    g_k[base + 64] = k1 * s + k2 * c;
}

// ---------------------------------------------------------------------------
// Causal flash attention, fp32.
// Grid: (T/64, B*H). Block: 256 threads as (tx 0..15, ty 0..15).
// Each thread: 4 q-rows (ty*4+i). S microtile 4x4 over 64x64 tile;
// O microtile 4 rows x 8 cols (tx*8).
// smem: Qt[128][65], Kt[128][65] (k-major, stride 65 vs bank conflicts),
//       Vs[64][128], Pst[64][68] (P transposed, float4-readable).
// ---------------------------------------------------------------------------
#define QT_STRIDE 65
#define PS_STRIDE 68
#define ATTN_SMEM_FLOATS (128 * QT_STRIDE * 2 + 64 * 128 + 64 * PS_STRIDE)
#define ATTN_SMEM_BYTES  (ATTN_SMEM_FLOATS * 4)

__global__ void __launch_bounds__(256) attn_kernel()
{
    extern __shared__ float sm[];
    float* Qt  = sm;                         // [128][65]
    float* Kt  = Qt + 128 * QT_STRIDE;       // [128][65]
    float* Vs  = Kt + 128 * QT_STRIDE;       // [64][128]
    float* Pst = Vs + 64 * 128;              // [64][68]  Pst[n][m]

    const int t  = threadIdx.x;
    const int tx = t & 15;
    const int ty = t >> 4;
    const int qt = blockIdx.x;               // q tile index (0..31)
    const int bh = blockIdx.y;
    const int b  = bh >> 4;
    const int h  = bh & 15;

    const float* qbase = g_q + (size_t)b * TSEQ * D_MODEL + h * DHEAD;
    const float* kbase = g_k + (size_t)b * TSEQ * D_MODEL + h * DHEAD;
    const float* vbase = g_v + (size_t)b * TSEQ * D_MODEL + h * DHEAD;
    float*       obase = g_o + (size_t)b * TSEQ * D_MODEL + h * DHEAD;

    const float scale = 0.08838834764831845f;   // 1/sqrt(128)

    // Load Q tile, scaled, transposed to Qt[d][m]
#pragma unroll
    for (int it = 0; it < 8; it++) {
        int idx = t + it * 256;
        int row = idx >> 5;
        int c4  = (idx & 31) << 2;
        float4 v = *(const float4*)&qbase[(size_t)(qt * 64 + row) * D_MODEL + c4];
        Qt[(c4 + 0) * QT_STRIDE + row] = v.x * scale;
        Qt[(c4 + 1) * QT_STRIDE + row] = v.y * scale;
        Qt[(c4 + 2) * QT_STRIDE + row] = v.z * scale;
        Qt[(c4 + 3) * QT_STRIDE + row] = v.w * scale;
    }

    float m_i[4], l_i[4], acc[4][8];
#pragma unroll
    for (int i = 0; i < 4; i++) {
        m_i[i] = -1e30f;
        l_i[i] = 0.0f;
#pragma unroll
        for (int j = 0; j < 8; j++) acc[i][j] = 0.0f;
    }

    for (int j = 0; j <= qt; j++) {
        // Load K tile (transposed) and V tile (row-major)
#pragma unroll
        for (int it = 0; it < 8; it++) {
            int idx = t + it * 256;
            int row = idx >> 5;
            int c4  = (idx & 31) << 2;
            float4 kv = *(const float4*)&kbase[(size_t)(j * 64 + row) * D_MODEL + c4];
            Kt[(c4 + 0) * QT_STRIDE + row] = kv.x;
            Kt[(c4 + 1) * QT_STRIDE + row] = kv.y;
            Kt[(c4 + 2) * QT_STRIDE + row] = kv.z;
            Kt[(c4 + 3) * QT_STRIDE + row] = kv.w;
            float4 vv = *(const float4*)&vbase[(size_t)(j * 64 + row) * D_MODEL + c4];
            *(float4*)&Vs[row * 128 + c4] = vv;
        }
        __syncthreads();

        // S = (Q*scale) @ K^T  (4x4 per thread)
        float s[4][4];
#pragma unroll
        for (int i = 0; i < 4; i++)
#pragma unroll
            for (int jj = 0; jj < 4; jj++) s[i][jj] = 0.0f;

#pragma unroll 8
        for (int k = 0; k < 128; k++) {
            float a0 = Qt[k * QT_STRIDE + ty * 4 + 0];
            float a1 = Qt[k * QT_STRIDE + ty * 4 + 1];
            float a2 = Qt[k * QT_STRIDE + ty * 4 + 2];
            float a3 = Qt[k * QT_STRIDE + ty * 4 + 3];
            float c0 = Kt[k * QT_STRIDE + tx * 4 + 0];
            float c1 = Kt[k * QT_STRIDE + tx * 4 + 1];
            float c2 = Kt[k * QT_STRIDE + tx * 4 + 2];
            float c3 = Kt[k * QT_STRIDE + tx * 4 + 3];
            s[0][0] = fmaf(a0, c0, s[0][0]); s[0][1] = fmaf(a0, c1, s[0][1]);
            s[0][2] = fmaf(a0, c2, s[0][2]); s[0][3] = fmaf(a0, c3, s[0][3]);
            s[1][0] = fmaf(a1, c0, s[1][0]); s[1][1] = fmaf(a1, c1, s[1][1]);
            s[1][2] = fmaf(a1, c2, s[1][2]); s[1][3] = fmaf(a1, c3, s[1][3]);
            s[2][0] = fmaf(a2, c0, s[2][0]); s[2][1] = fmaf(a2, c1, s[2][1]);
            s[2][2] = fmaf(a2, c2, s[2][2]); s[2][3] = fmaf(a2, c3, s[2][3]);
            s[3][0] = fmaf(a3, c0, s[3][0]); s[3][1] = fmaf(a3, c1, s[3][1]);
            s[3][2] = fmaf(a3, c2, s[3][2]); s[3][3] = fmaf(a3, c3, s[3][3]);
        }

        // Causal mask on the diagonal tile
        if (j == qt) {
#pragma unroll
            for (int i = 0; i < 4; i++)
#pragma unroll
                for (int jj = 0; jj < 4; jj++)
                    if (tx * 4 + jj > ty * 4 + i) s[i][jj] = -1e30f;
        }

        // Online softmax update per row
#pragma unroll
        for (int i = 0; i < 4; i++) {
            float rm = fmaxf(fmaxf(s[i][0], s[i][1]), fmaxf(s[i][2], s[i][3]));
            rm = fmaxf(rm, __shfl_xor_sync(0xffffffffu, rm, 1));
            rm = fmaxf(rm, __shfl_xor_sync(0xffffffffu, rm, 2));
            rm = fmaxf(rm, __shfl_xor_sync(0xffffffffu, rm, 4));
            rm = fmaxf(rm, __shfl_xor_sync(0xffffffffu, rm, 8));
            float mn = fmaxf(m_i[i], rm);
            float al = __expf(m_i[i] - mn);
            float rs = 0.0f;
#pragma unroll
            for (int jj = 0; jj < 4; jj++) {
                float p = __expf(s[i][jj] - mn);
                s[i][jj] = p;
                rs += p;
            }
            rs += __shfl_xor_sync(0xffffffffu, rs, 1);
            rs += __shfl_xor_sync(0xffffffffu, rs, 2);
            rs += __shfl_xor_sync(0xffffffffu, rs, 4);
            rs += __shfl_xor_sync(0xffffffffu, rs, 8);
            l_i[i] = l_i[i] * al + rs;
            m_i[i] = mn;
#pragma unroll
            for (int jc = 0; jc < 8; jc++) acc[i][jc] *= al;
#pragma unroll
            for (int jj = 0; jj < 4; jj++)
                Pst[(tx * 4 + jj) * PS_STRIDE + ty * 4 + i] = s[i][jj];
        }
        __syncthreads();

        // O += P @ V
#pragma unroll 4
        for (int n = 0; n < 64; n++) {
            float4 pr = *(const float4*)&Pst[n * PS_STRIDE + ty * 4];
            float4 v0 = *(const float4*)&Vs[n * 128 + tx * 8];
            float4 v1 = *(const float4*)&Vs[n * 128 + tx * 8 + 4];
            float pv[4] = {pr.x, pr.y, pr.z, pr.w};
            float vv[8] = {v0.x, v0.y, v0.z, v0.w, v1.x, v1.y, v1.z, v1.w};
#pragma unroll
            for (int i = 0; i < 4; i++)
#pragma unroll
                for (int jc = 0; jc < 8; jc++)
                    acc[i][jc] = fmaf(pv[i], vv[jc], acc[i][jc]);
        }
        __syncthreads();
    }

    // Normalize and write O in (B,T,H,D) layout
#pragma unroll
    for (int i = 0; i < 4; i++) {
        float inv = 1.0f / l_i[i];
        int row = qt * 64 + ty * 4 + i;
        float4 o0, o1;
        o0.x = acc[i][0] * inv; o0.y = acc[i][1] * inv;
        o0.z = acc[i][2] * inv; o0.w = acc[i][3] * inv;
        o1.x = acc[i][4] * inv; o1.y = acc[i][5] * inv;
        o1.z = acc[i][6] * inv; o1.w = acc[i][7] * inv;
        float* orow = obase + (size_t)row * D_MODEL + tx * 8;
        *(float4*)&orow[0] = o0;
        *(float4*)&orow[4] = o1;
    }
}

// ---------------------------------------------------------------------------
// Launch
// Inputs (metadata order): x, Wq, bq, Wk, bk, Wv, bv, Wo, bo, sin, cos
// ---------------------------------------------------------------------------
extern "C" void kernel_launch(void* const* d_in, const int* in_sizes, int n_in,
                              void* d_out, int out_size)
{
    const float* x   = (const float*)d_in[0];
    const float* Wq  = (const float*)d_in[1];
    const float* bq  = (const float*)d_in[2];
    const float* Wk  = (const float*)d_in[3];
    const float* bk  = (const float*)d_in[4];
    const float* Wv  = (const float*)d_in[5];
    const float* bv  = (const float*)d_in[6];
    const float* Wo  = (const float*)d_in[7];
    const float* bo  = (const float*)d_in[8];
    const float* sn  = (const float*)d_in[9];
    const float* cs  = (const float*)d_in[10];
    float* out = (float*)d_out;

    float *q_ptr, *k_ptr, *v_ptr, *o_ptr;
    cudaGetSymbolAddress((void**)&q_ptr, g_q);
    cudaGetSymbolAddress((void**)&k_ptr, g_k);
    cudaGetSymbolAddress((void**)&v_ptr, g_v);
    cudaGetSymbolAddress((void**)&o_ptr, g_o);

    // 1. QKV projections (fused into one launch via blockIdx.z)
    {
        dim3 grid(D_MODEL / 128, MROWS / 128, 3);
        gemm_bias_kernel<<<grid, 256>>>(x, Wq, Wk, Wv, bq, bk, bv,
                                        q_ptr, k_ptr, v_ptr);
    }

    // 2. RoPE in place on q, k
    {
        int total = MROWS * NHEADS * 64;
        rope_kernel<<<(total + 255) / 256, 256>>>(sn, cs);
    }

    // 3. Causal flash attention
    {
        static int smem_set = 0;
        cudaFuncSetAttribute(attn_kernel,
                             cudaFuncAttributeMaxDynamicSharedMemorySize,
                             ATTN_SMEM_BYTES);
        (void)smem_set;
        dim3 grid(TSEQ / 64, BATCH * NHEADS);
        attn_kernel<<<grid, 256, ATTN_SMEM_BYTES>>>();
    }

    // 4. Output projection
    {
        dim3 grid(D_MODEL / 128, MROWS / 128, 1);
        gemm_bias_kernel<<<grid, 256>>>(o_ptr, Wo, Wo, Wo, bo, bo, bo,
                                        out, out, out);
    }
}

// round 4
// speedup vs baseline: 1.8509x; 1.8509x over previous
#include <cuda_runtime.h>
#include <cuda_bf16.h>
#include <math.h>
#include <stdint.h>

#define D_MODEL 2048
#define NHEADS  16
#define DHEAD   128
#define TSEQ    2048
#define BATCH   2
#define MROWS   (BATCH * TSEQ)   // 4096

// ---------------------------------------------------------------------------
// Scratch (allocation-free rule: static __device__ arrays)
// ---------------------------------------------------------------------------
__device__ float g_q[(size_t)MROWS * D_MODEL];
__device__ float g_k[(size_t)MROWS * D_MODEL];
__device__ float g_v[(size_t)MROWS * D_MODEL];
__device__ float g_o[(size_t)MROWS * D_MODEL];

__device__ __nv_bfloat16 g_xh[(size_t)MROWS * D_MODEL];
__device__ __nv_bfloat16 g_xl[(size_t)MROWS * D_MODEL];
__device__ __nv_bfloat16 g_oh[(size_t)MROWS * D_MODEL];
__device__ __nv_bfloat16 g_ol[(size_t)MROWS * D_MODEL];
__device__ __nv_bfloat16 g_wh[(size_t)4 * D_MODEL * D_MODEL];
__device__ __nv_bfloat16 g_wl[(size_t)4 * D_MODEL * D_MODEL];

// ---------------------------------------------------------------------------
// PTX helpers (compute_100-portable: ldmatrix / mma.sync / cp.async)
// ---------------------------------------------------------------------------
__device__ __forceinline__ uint32_t smem_u32(const void* p) {
    uint32_t a;
    asm("{ .reg .u64 t; cvta.to.shared.u64 t, %1; cvt.u32.u64 %0, t; }"
        : "=r"(a) : "l"(p));
    return a;
}

__device__ __forceinline__ void cp16(uint32_t saddr, const void* g) {
    asm volatile("cp.async.cg.shared.global [%0], [%1], 16;"
                 :: "r"(saddr), "l"(g) : "memory");
}
__device__ __forceinline__ void cp_commit() {
    asm volatile("cp.async.commit_group;" ::: "memory");
}
__device__ __forceinline__ void cp_wait1() {
    asm volatile("cp.async.wait_group 1;" ::: "memory");
}
__device__ __forceinline__ void cp_wait0() {
    asm volatile("cp.async.wait_group 0;" ::: "memory");
}

__device__ __forceinline__ void ldsm_x4(uint32_t& r0, uint32_t& r1,
                                        uint32_t& r2, uint32_t& r3, uint32_t a) {
    asm volatile("ldmatrix.sync.aligned.m8n8.x4.shared.b16 {%0,%1,%2,%3}, [%4];"
                 : "=r"(r0), "=r"(r1), "=r"(r2), "=r"(r3) : "r"(a));
}
__device__ __forceinline__ void ldsm_x2(uint32_t& r0, uint32_t& r1, uint32_t a) {
    asm volatile("ldmatrix.sync.aligned.m8n8.x2.shared.b16 {%0,%1}, [%2];"
                 : "=r"(r0), "=r"(r1) : "r"(a));
}

__device__ __forceinline__ void mma_bf16(float& c0, float& c1, float& c2, float& c3,
                                         uint32_t a0, uint32_t a1, uint32_t a2, uint32_t a3,
                                         uint32_t b0, uint32_t b1) {
    asm volatile(
        "mma.sync.aligned.m16n8k16.row.col.f32.bf16.bf16.f32 "
        "{%0,%1,%2,%3}, {%4,%5,%6,%7}, {%8,%9}, {%0,%1,%2,%3};"
        : "+f"(c0), "+f"(c1), "+f"(c2), "+f"(c3)
        : "r"(a0), "r"(a1), "r"(a2), "r"(a3), "r"(b0), "r"(b1));
}

// Swizzled byte offset within a [128 rows x 64B] tile.
// 64B rows = 4 x 16B chunks; chunk ^= (row>>1)&3 -> conflict-free ldmatrix/STS.
__device__ __forceinline__ uint32_t tile_off(int row, int kbyte) {
    return row * 64 + ((((kbyte >> 4) ^ ((row >> 1) & 3)) << 4) | (kbyte & 15));
}

// ---------------------------------------------------------------------------
// Split fp32 -> (hi, lo) bf16 pair. n4 = element count / 4.
// ---------------------------------------------------------------------------
__global__ void split_kernel(const float* __restrict__ in,
                             __nv_bfloat16* __restrict__ hi,
                             __nv_bfloat16* __restrict__ lo, int n4)
{
    int i = blockIdx.x * blockDim.x + threadIdx.x;
    if (i >= n4) return;
    float4 a = ((const float4*)in)[i];
    __nv_bfloat16 h0 = __float2bfloat16(a.x);
    __nv_bfloat16 h1 = __float2bfloat16(a.y);
    __nv_bfloat16 h2 = __float2bfloat16(a.z);
    __nv_bfloat16 h3 = __float2bfloat16(a.w);
    __nv_bfloat16 l0 = __float2bfloat16(a.x - __bfloat162float(h0));
    __nv_bfloat16 l1 = __float2bfloat16(a.y - __bfloat162float(h1));
    __nv_bfloat16 l2 = __float2bfloat16(a.z - __bfloat162float(h2));
    __nv_bfloat16 l3 = __float2bfloat16(a.w - __bfloat162float(h3));
    __nv_bfloat162* hp = (__nv_bfloat162*)hi;
    __nv_bfloat162* lp = (__nv_bfloat162*)lo;
    hp[2 * i]     = __nv_bfloat162(h0, h1);
    hp[2 * i + 1] = __nv_bfloat162(h2, h3);
    lp[2 * i]     = __nv_bfloat162(l0, l1);
    lp[2 * i + 1] = __nv_bfloat162(l2, l3);
}

// ---------------------------------------------------------------------------
// mma.sync GEMM: C[M,N] = A @ W^T + bias, A,W pre-split into bf16 hi/lo.
// 3 mma passes: Ah*Bh + Al*Bh + Ah*Bl (effective ~2^-17 precision).
// CTA 128x128, BK=32, 8 warps as 4(M) x 2(N), warp tile 32x64.
// 2-stage cp.async double buffer. blockIdx.z selects (W, bias, C) set.
// ---------------------------------------------------------------------------
#define BK 32
#define NCHUNK (D_MODEL / BK)          // 64
#define TILE_B (128 * 64)              // 8 KB per bf16 tile (128 rows x 64B)
#define STAGE_B (4 * TILE_B)           // Ah, Al, Bh, Bl = 32 KB
#define GEMM_SMEM_BYTES (2 * STAGE_B)  // 64 KB

__global__ void __launch_bounds__(256) gemm_mma_kernel(
    const __nv_bfloat16* __restrict__ Ah, const __nv_bfloat16* __restrict__ Al,
    const __nv_bfloat16* __restrict__ Wh0, const __nv_bfloat16* __restrict__ Wl0,
    const __nv_bfloat16* __restrict__ Wh1, const __nv_bfloat16* __restrict__ Wl1,
    const __nv_bfloat16* __restrict__ Wh2, const __nv_bfloat16* __restrict__ Wl2,
    const float* __restrict__ b0, const float* __restrict__ b1, const float* __restrict__ b2,
    float* __restrict__ C0, float* __restrict__ C1, float* __restrict__ C2)
{
    extern __shared__ char sm[];
    const __nv_bfloat16 *Wh, *Wl;
    const float* bias;
    float* C;
    if (blockIdx.z == 0)      { Wh = Wh0; Wl = Wl0; bias = b0; C = C0; }
    else if (blockIdx.z == 1) { Wh = Wh1; Wl = Wl1; bias = b1; C = C1; }
    else                      { Wh = Wh2; Wl = Wl2; bias = b2; C = C2; }

    const int t    = threadIdx.x;
    const int wid  = t >> 5;
    const int lane = t & 31;
    const int wm   = wid & 3;          // 0..3 (M)
    const int wn   = wid >> 2;         // 0..1 (N)
    const int n0   = blockIdx.x * 128;
    const int m0   = blockIdx.y * 128;

    const uint32_t smb = smem_u32(sm);

    // Loader: 512 16B chunks per tile; this thread handles chunks t and t+256.
    // chunk idx -> row = idx>>2, c = idx&3 (16B within 64B row)
    const int lrow0 = t >> 2,            lc0 = t & 3;
    const int lrow1 = (t + 256) >> 2,    lc1 = t & 3;   // (t+256)&3 == t&3
    const uint32_t so0 = tile_off(lrow0, lc0 * 16);
    const uint32_t so1 = tile_off(lrow1, lc1 * 16);

    // ldmatrix source offsets (within a tile), ks=0; ks=1 toggles bit 5 (^32).
    const int gmq  = lane & 7;
    const int quad = lane >> 3;
    uint32_t aoff[2];
#pragma unroll
    for (int mt = 0; mt < 2; mt++) {
        int row = wm * 32 + mt * 16 + (quad & 1) * 8 + gmq;
        aoff[mt] = tile_off(row, (quad >> 1) * 16);
    }
    uint32_t boff[8];
    {
        int l16 = lane & 15;
#pragma unroll
        for (int nt = 0; nt < 8; nt++) {
            int row = wn * 64 + nt * 8 + (l16 & 7);
            boff[nt] = tile_off(row, (l16 >> 3) * 16);
        }
    }

    // Bias values for this thread's output columns (2 per n-tile)
    float bsv[8][2];
#pragma unroll
    for (int nt = 0; nt < 8; nt++) {
        int col = n0 + wn * 64 + nt * 8 + (lane & 3) * 2;
        bsv[nt][0] = bias[col];
        bsv[nt][1] = bias[col + 1];
    }

    float acc[2][8][4];
#pragma unroll
    for (int mt = 0; mt < 2; mt++)
#pragma unroll
        for (int nt = 0; nt < 8; nt++)
#pragma unroll
            for (int r = 0; r < 4; r++) acc[mt][nt][r] = 0.0f;

    auto load_stage = [&](int c, int s) {
        const uint32_t st = smb + s * STAGE_B;
        const int k0 = c * BK;
        const __nv_bfloat16* gah = Ah + (size_t)(m0 + lrow0) * D_MODEL + k0 + lc0 * 8;
        const __nv_bfloat16* gal = Al + (size_t)(m0 + lrow0) * D_MODEL + k0 + lc0 * 8;
        const __nv_bfloat16* gbh = Wh + (size_t)(n0 + lrow0) * D_MODEL + k0 + lc0 * 8;
        const __nv_bfloat16* gbl = Wl + (size_t)(n0 + lrow0) * D_MODEL + k0 + lc0 * 8;
        cp16(st + 0 * TILE_B + so0, gah);
        cp16(st + 1 * TILE_B + so0, gal);
        cp16(st + 2 * TILE_B + so0, gbh);
        cp16(st + 3 * TILE_B + so0, gbl);
        const __nv_bfloat16* gah1 = Ah + (size_t)(m0 + lrow1) * D_MODEL + k0 + lc1 * 8;
        const __nv_bfloat16* gal1 = Al + (size_t)(m0 + lrow1) * D_MODEL + k0 + lc1 * 8;
        const __nv_bfloat16* gbh1 = Wh + (size_t)(n0 + lrow1) * D_MODEL + k0 + lc1 * 8;
        const __nv_bfloat16* gbl1 = Wl + (size_t)(n0 + lrow1) * D_MODEL + k0 + lc1 * 8;
        cp16(st + 0 * TILE_B + so1, gah1);
        cp16(st + 1 * TILE_B + so1, gal1);
        cp16(st + 2 * TILE_B + so1, gbh1);
        cp16(st + 3 * TILE_B + so1, gbl1);
    };

    load_stage(0, 0);
    cp_commit();

    for (int c = 0; c < NCHUNK; c++) {
        if (c + 1 < NCHUNK) {
            load_stage(c + 1, (c + 1) & 1);
            cp_commit();
            cp_wait1();
        } else {
            cp_wait0();
        }
        __syncthreads();

        const uint32_t st = smb + (c & 1) * STAGE_B;
#pragma unroll
        for (int ks = 0; ks < 2; ks++) {
            const uint32_t kx = ks * 32;
            uint32_t ah[2][4], al[2][4];
#pragma unroll
            for (int mt = 0; mt < 2; mt++) {
                ldsm_x4(ah[mt][0], ah[mt][1], ah[mt][2], ah[mt][3],
                        st + 0 * TILE_B + (aoff[mt] ^ kx));
                ldsm_x4(al[mt][0], al[mt][1], al[mt][2], al[mt][3],
                        st + 1 * TILE_B + (aoff[mt] ^ kx));
            }
#pragma unroll
            for (int nt = 0; nt < 8; nt++) {
                uint32_t bh0, bh1, bl0, bl1;
                ldsm_x2(bh0, bh1, st + 2 * TILE_B + (boff[nt] ^ kx));
                ldsm_x2(bl0, bl1, st + 3 * TILE_B + (boff[nt] ^ kx));
#pragma unroll
                for (int mt = 0; mt < 2; mt++) {
                    mma_bf16(acc[mt][nt][0], acc[mt][nt][1], acc[mt][nt][2], acc[mt][nt][3],
                             ah[mt][0], ah[mt][1], ah[mt][2], ah[mt][3], bh0, bh1);
                    mma_bf16(acc[mt][nt][0], acc[mt][nt][1], acc[mt][nt][2], acc[mt][nt][3],
                             al[mt][0], al[mt][1], al[mt][2], al[mt][3], bh0, bh1);
                    mma_bf16(acc[mt][nt][0], acc[mt][nt][1], acc[mt][nt][2], acc[mt][nt][3],
                             ah[mt][0], ah[mt][1], ah[mt][2], ah[mt][3], bl0, bl1);
                }
            }
        }
        __syncthreads();
    }

    // Epilogue: + bias, store (float2 per fragment row)
#pragma unroll
    for (int mt = 0; mt < 2; mt++) {
        int r0 = m0 + wm * 32 + mt * 16 + (lane >> 2);
#pragma unroll
        for (int nt = 0; nt < 8; nt++) {
            int col = n0 + wn * 64 + nt * 8 + (lane & 3) * 2;
            float2 v0, v1;
            v0.x = acc[mt][nt][0] + bsv[nt][0];
            v0.y = acc[mt][nt][1] + bsv[nt][1];
            v1.x = acc[mt][nt][2] + bsv[nt][0];
            v1.y = acc[mt][nt][3] + bsv[nt][1];
            *(float2*)(C + (size_t)r0 * D_MODEL + col)       = v0;
            *(float2*)(C + (size_t)(r0 + 8) * D_MODEL + col) = v1;
        }
    }
}

// ---------------------------------------------------------------------------
// RoPE in-place on g_q and g_k, layout (B,T,H,D) == [B*T, 2048].
// ---------------------------------------------------------------------------
__global__ void rope_kernel(const float* __restrict__ sin_t,
                            const float* __restrict__ cos_t)
{
    int idx = blockIdx.x * blockDim.x + threadIdx.x;
    if (idx >= MROWS * NHEADS * 64) return;
    int i   = idx & 63;
    int h   = (idx >> 6) & (NHEADS - 1);
    int row = idx >> 10;
    int tpos = row & (TSEQ - 1);

    float s = sin_t[tpos * 64 + i];
    float c = cos_t[tpos * 64 + i];

    size_t base = (size_t)row * D_MODEL + h * DHEAD + i;
    float q1 = g_q[base], q2 = g_q[base + 64];
    g_q[base]      = q1 * c - q2 * s;
    g_q[base + 64] = q1 * s + q2 * c;
    float k1 = g_k[base], k2 = g_k[base + 64];
    g_k[base]      = k1 * c - k2 * s;
    g_k[base + 64] = k1 * s + k2 * c;
}

// ---------------------------------------------------------------------------
// Causal flash attention, fp32 (round-1 passing version, unchanged).
// ---------------------------------------------------------------------------
#define QT_STRIDE 65
#define PS_STRIDE 68
#define ATTN_SMEM_FLOATS (128 * QT_STRIDE * 2 + 64 * 128 + 64 * PS_STRIDE)
#define ATTN_SMEM_BYTES  (ATTN_SMEM_FLOATS * 4)

__global__ void __launch_bounds__(256) attn_kernel()
{
    extern __shared__ float smf[];
    float* Qt  = smf;
    float* Kt  = Qt + 128 * QT_STRIDE;
    float* Vs  = Kt + 128 * QT_STRIDE;
    float* Pst = Vs + 64 * 128;

    const int t  = threadIdx.x;
    const int tx = t & 15;
    const int ty = t >> 4;
    const int qt = blockIdx.x;
    const int bh = blockIdx.y;
    const int b  = bh >> 4;
    const int h  = bh & 15;

    const float* qbase = g_q + (size_t)b * TSEQ * D_MODEL + h * DHEAD;
    const float* kbase = g_k + (size_t)b * TSEQ * D_MODEL + h * DHEAD;
    const float* vbase = g_v + (size_t)b * TSEQ * D_MODEL + h * DHEAD;
    float*       obase = g_o + (size_t)b * TSEQ * D_MODEL + h * DHEAD;

    const float scale = 0.08838834764831845f;

#pragma unroll
    for (int it = 0; it < 8; it++) {
        int idx = t + it * 256;
        int row = idx >> 5;
        int c4  = (idx & 31) << 2;
        float4 v = *(const float4*)&qbase[(size_t)(qt * 64 + row) * D_MODEL + c4];
        Qt[(c4 + 0) * QT_STRIDE + row] = v.x * scale;
        Qt[(c4 + 1) * QT_STRIDE + row] = v.y * scale;
        Qt[(c4 + 2) * QT_STRIDE + row] = v.z * scale;
        Qt[(c4 + 3) * QT_STRIDE + row] = v.w * scale;
    }

    float m_i[4], l_i[4], acc[4][8];
#pragma unroll
    for (int i = 0; i < 4; i++) {
        m_i[i] = -1e30f;
        l_i[i] = 0.0f;
#pragma unroll
        for (int j = 0; j < 8; j++) acc[i][j] = 0.0f;
    }

    for (int j = 0; j <= qt; j++) {
#pragma unroll
        for (int it = 0; it < 8; it++) {
            int idx = t + it * 256;
            int row = idx >> 5;
            int c4  = (idx & 31) << 2;
            float4 kv = *(const float4*)&kbase[(size_t)(j * 64 + row) * D_MODEL + c4];
            Kt[(c4 + 0) * QT_STRIDE + row] = kv.x;
            Kt[(c4 + 1) * QT_STRIDE + row] = kv.y;
            Kt[(c4 + 2) * QT_STRIDE + row] = kv.z;
            Kt[(c4 + 3) * QT_STRIDE + row] = kv.w;
            float4 vv = *(const float4*)&vbase[(size_t)(j * 64 + row) * D_MODEL + c4];
            *(float4*)&Vs[row * 128 + c4] = vv;
        }
        __syncthreads();

        float s[4][4];
#pragma unroll
        for (int i = 0; i < 4; i++)
#pragma unroll
            for (int jj = 0; jj < 4; jj++) s[i][jj] = 0.0f;

#pragma unroll 8
        for (int k = 0; k < 128; k++) {
            float a0 = Qt[k * QT_STRIDE + ty * 4 + 0];
            float a1 = Qt[k * QT_STRIDE + ty * 4 + 1];
            float a2 = Qt[k * QT_STRIDE + ty * 4 + 2];
            float a3 = Qt[k * QT_STRIDE + ty * 4 + 3];
            float c0 = Kt[k * QT_STRIDE + tx * 4 + 0];
            float c1 = Kt[k * QT_STRIDE + tx * 4 + 1];
            float c2 = Kt[k * QT_STRIDE + tx * 4 + 2];
            float c3 = Kt[k * QT_STRIDE + tx * 4 + 3];
            s[0][0] = fmaf(a0, c0, s[0][0]); s[0][1] = fmaf(a0, c1, s[0][1]);
            s[0][2] = fmaf(a0, c2, s[0][2]); s[0][3] = fmaf(a0, c3, s[0][3]);
            s[1][0] = fmaf(a1, c0, s[1][0]); s[1][1] = fmaf(a1, c1, s[1][1]);
            s[1][2] = fmaf(a1, c2, s[1][2]); s[1][3] = fmaf(a1, c3, s[1][3]);
            s[2][0] = fmaf(a2, c0, s[2][0]); s[2][1] = fmaf(a2, c1, s[2][1]);
            s[2][2] = fmaf(a2, c2, s[2][2]); s[2][3] = fmaf(a2, c3, s[2][3]);
            s[3][0] = fmaf(a3, c0, s[3][0]); s[3][1] = fmaf(a3, c1, s[3][1]);
            s[3][2] = fmaf(a3, c2, s[3][2]); s[3][3] = fmaf(a3, c3, s[3][3]);
        }

        if (j == qt) {
#pragma unroll
            for (int i = 0; i < 4; i++)
#pragma unroll
                for (int jj = 0; jj < 4; jj++)
                    if (tx * 4 + jj > ty * 4 + i) s[i][jj] = -1e30f;
        }

#pragma unroll
        for (int i = 0; i < 4; i++) {
            float rm = fmaxf(fmaxf(s[i][0], s[i][1]), fmaxf(s[i][2], s[i][3]));
            rm = fmaxf(rm, __shfl_xor_sync(0xffffffffu, rm, 1));
            rm = fmaxf(rm, __shfl_xor_sync(0xffffffffu, rm, 2));
            rm = fmaxf(rm, __shfl_xor_sync(0xffffffffu, rm, 4));
            rm = fmaxf(rm, __shfl_xor_sync(0xffffffffu, rm, 8));
            float mn = fmaxf(m_i[i], rm);
            float al = __expf(m_i[i] - mn);
            float rs = 0.0f;
#pragma unroll
            for (int jj = 0; jj < 4; jj++) {
                float p = __expf(s[i][jj] - mn);
                s[i][jj] = p;
                rs += p;
            }
            rs += __shfl_xor_sync(0xffffffffu, rs, 1);
            rs += __shfl_xor_sync(0xffffffffu, rs, 2);
            rs += __shfl_xor_sync(0xffffffffu, rs, 4);
            rs += __shfl_xor_sync(0xffffffffu, rs, 8);
            l_i[i] = l_i[i] * al + rs;
            m_i[i] = mn;
#pragma unroll
            for (int jc = 0; jc < 8; jc++) acc[i][jc] *= al;
#pragma unroll
            for (int jj = 0; jj < 4; jj++)
                Pst[(tx * 4 + jj) * PS_STRIDE + ty * 4 + i] = s[i][jj];
        }
        __syncthreads();

#pragma unroll 4
        for (int n = 0; n < 64; n++) {
            float4 pr = *(const float4*)&Pst[n * PS_STRIDE + ty * 4];
            float4 v0 = *(const float4*)&Vs[n * 128 + tx * 8];
            float4 v1 = *(const float4*)&Vs[n * 128 + tx * 8 + 4];
            float pv[4] = {pr.x, pr.y, pr.z, pr.w};
            float vv[8] = {v0.x, v0.y, v0.z, v0.w, v1.x, v1.y, v1.z, v1.w};
#pragma unroll
            for (int i = 0; i < 4; i++)
#pragma unroll
                for (int jc = 0; jc < 8; jc++)
                    acc[i][jc] = fmaf(pv[i], vv[jc], acc[i][jc]);
        }
        __syncthreads();
    }

#pragma unroll
    for (int i = 0; i < 4; i++) {
        float inv = 1.0f / l_i[i];
        int row = qt * 64 + ty * 4 + i;
        float4 o0, o1;
        o0.x = acc[i][0] * inv; o0.y = acc[i][1] * inv;
        o0.z = acc[i][2] * inv; o0.w = acc[i][3] * inv;
        o1.x = acc[i][4] * inv; o1.y = acc[i][5] * inv;
        o1.z = acc[i][6] * inv; o1.w = acc[i][7] * inv;
        float* orow = obase + (size_t)row * D_MODEL + tx * 8;
        *(float4*)&orow[0] = o0;
        *(float4*)&orow[4] = o1;
    }
}

// ---------------------------------------------------------------------------
// Launch. Inputs: x, Wq, bq, Wk, bk, Wv, bv, Wo, bo, sin, cos
// ---------------------------------------------------------------------------
extern "C" void kernel_launch(void* const* d_in, const int* in_sizes, int n_in,
                              void* d_out, int out_size)
{
    const float* x   = (const float*)d_in[0];
    const float* Wq  = (const float*)d_in[1];
    const float* bq  = (const float*)d_in[2];
    const float* Wk  = (const float*)d_in[3];
    const float* bk  = (const float*)d_in[4];
    const float* Wv  = (const float*)d_in[5];
    const float* bv  = (const float*)d_in[6];
    const float* Wo  = (const float*)d_in[7];
    const float* bo  = (const float*)d_in[8];
    const float* sn  = (const float*)d_in[9];
    const float* cs  = (const float*)d_in[10];
    float* out = (float*)d_out;

    float *q_ptr, *k_ptr, *v_ptr, *o_ptr;
    cudaGetSymbolAddress((void**)&q_ptr, g_q);
    cudaGetSymbolAddress((void**)&k_ptr, g_k);
    cudaGetSymbolAddress((void**)&v_ptr, g_v);
    cudaGetSymbolAddress((void**)&o_ptr, g_o);

    __nv_bfloat16 *xh, *xl, *oh, *ol, *wh, *wl;
    cudaGetSymbolAddress((void**)&xh, g_xh);
    cudaGetSymbolAddress((void**)&xl, g_xl);
    cudaGetSymbolAddress((void**)&oh, g_oh);
    cudaGetSymbolAddress((void**)&ol, g_ol);
    cudaGetSymbolAddress((void**)&wh, g_wh);
    cudaGetSymbolAddress((void**)&wl, g_wl);

    const size_t WSZ = (size_t)D_MODEL * D_MODEL;   // 4M
    const int wq4 = (int)(WSZ / 4);
    const int x4  = (int)((size_t)MROWS * D_MODEL / 4);

    cudaFuncSetAttribute(gemm_mma_kernel,
                         cudaFuncAttributeMaxDynamicSharedMemorySize,
                         GEMM_SMEM_BYTES);
    cudaFuncSetAttribute(attn_kernel,
                         cudaFuncAttributeMaxDynamicSharedMemorySize,
                         ATTN_SMEM_BYTES);

    // 0. Split inputs and weights to bf16 hi/lo
    split_kernel<<<(x4 + 255) / 256, 256>>>(x, xh, xl, x4);
    split_kernel<<<(wq4 + 255) / 256, 256>>>(Wq, wh + 0 * WSZ, wl + 0 * WSZ, wq4);
    split_kernel<<<(wq4 + 255) / 256, 256>>>(Wk, wh + 1 * WSZ, wl + 1 * WSZ, wq4);
    split_kernel<<<(wq4 + 255) / 256, 256>>>(Wv, wh + 2 * WSZ, wl + 2 * WSZ, wq4);
    split_kernel<<<(wq4 + 255) / 256, 256>>>(Wo, wh + 3 * WSZ, wl + 3 * WSZ, wq4);

    // 1. QKV projections on tensor cores (mma.sync)
    {
        dim3 grid(D_MODEL / 128, MROWS / 128, 3);
        gemm_mma_kernel<<<grid, 256, GEMM_SMEM_BYTES>>>(
            xh, xl,
            wh + 0 * WSZ, wl + 0 * WSZ,
            wh + 1 * WSZ, wl + 1 * WSZ,
            wh + 2 * WSZ, wl + 2 * WSZ,
            bq, bk, bv,
            q_ptr, k_ptr, v_ptr);
    }

    // 2. RoPE in place on q, k
    {
        int total = MROWS * NHEADS * 64;
        rope_kernel<<<(total + 255) / 256, 256>>>(sn, cs);
    }

    // 3. Causal flash attention (fp32)
    {
        dim3 grid(TSEQ / 64, BATCH * NHEADS);
        attn_kernel<<<grid, 256, ATTN_SMEM_BYTES>>>();
    }

    // 4. Split attention output, then output projection
    split_kernel<<<(x4 + 255) / 256, 256>>>(o_ptr, oh, ol, x4);
    {
        dim3 grid(D_MODEL / 128, MROWS / 128, 1);
        gemm_mma_kernel<<<grid, 256, GEMM_SMEM_BYTES>>>(
            oh, ol,
            wh + 3 * WSZ, wl + 3 * WSZ,
            wh + 3 * WSZ, wl + 3 * WSZ,
            wh + 3 * WSZ, wl + 3 * WSZ,
            bo, bo, bo,
            out, out, out);
    }
}